// round 15
// baseline (speedup 1.0000x reference)
#include <cuda_runtime.h>
#include <cuda_fp16.h>
#include <cstdint>

#define BB 4
#define NN 8192
#define KK 16
#define DD 128
#define GG 32
#define MM (BB*NN)          // 32768 rows
#define BN_EPS 1e-5f

#define NPART 2048          // gather blocks (16 points each) = stats partials
#define NMID 32             // stats stage-A output rows

// ---------------- scratch (device globals; no allocation) ----------------
__device__ __half g_h[(size_t)MM * DD];       // projected features, fp16, 8 MB
__device__ float g_psum [NPART][DD];
__device__ float g_psum2[NPART][DD];
__device__ float g_mid  [NMID][DD];
__device__ float g_mid2 [NMID][DD];
__device__ float g_scale[DD];
__device__ float g_shift[DD];
__device__ int   g_ctr = 0;                   // last-block ticket (self-resets)

// ---------------- mma / ldmatrix helpers ----------------------------------
#define LDSM4(r0, r1, r2, r3, addr)                                            \
    asm volatile("ldmatrix.sync.aligned.m8n8.x4.shared.b16 {%0,%1,%2,%3}, [%4];" \
                 : "=r"(r0), "=r"(r1), "=r"(r2), "=r"(r3) : "r"(addr))

__device__ __forceinline__ void mma_f16(float c[4],
                                        uint32_t a0, uint32_t a1, uint32_t a2, uint32_t a3,
                                        uint32_t b0, uint32_t b1) {
    asm volatile(
        "mma.sync.aligned.m16n8k16.row.col.f32.f16.f16.f32 "
        "{%0,%1,%2,%3}, {%4,%5,%6,%7}, {%8,%9}, {%0,%1,%2,%3};"
        : "+f"(c[0]), "+f"(c[1]), "+f"(c[2]), "+f"(c[3])
        : "r"(a0), "r"(a1), "r"(a2), "r"(a3), "r"(b0), "r"(b1));
}

// ---------------- kernel 1: H = X * W^T, single-term fp16 HMMA (R11) ------
#define BK 32
#define RS 40   // smem row stride in fp16 elems (80 B -> LDSM conflict-free)
__global__ void __launch_bounds__(256) gemm_kernel(const float* __restrict__ X,
                                                   const float* __restrict__ W,
                                                   __half* __restrict__ H) {
    __shared__ __half Xs[128 * RS];
    __shared__ __half Ws[128 * RS];

    const int tid  = threadIdx.x;
    const int warp = tid >> 5;
    const int lane = tid & 31;
    const int wm   = warp >> 1;
    const int wn   = warp & 1;
    const int m0   = blockIdx.x * 128;
    const int gr   = lane >> 2;
    const int gc   = lane & 3;
    const int l16  = lane & 15;
    const int kh   = (lane >> 4) << 3;

    float c[2][8][4];
#pragma unroll
    for (int i = 0; i < 2; i++)
#pragma unroll
        for (int j = 0; j < 8; j++)
#pragma unroll
            for (int t = 0; t < 4; t++) c[i][j][t] = 0.f;

    const uint32_t xs_b = (uint32_t)__cvta_generic_to_shared(Xs);
    const uint32_t ws_b = (uint32_t)__cvta_generic_to_shared(Ws);

    float4 px[4], pw[4];
#pragma unroll
    for (int i = 0; i < 4; i++) {
        const int q   = tid + i * 256;
        const int row = q >> 3;
        const int cq  = q & 7;
        px[i] = *(const float4*)(X + (size_t)(m0 + row) * DD + cq * 4);
        pw[i] = *(const float4*)(W + (size_t)row * DD + cq * 4);
    }

    for (int kcs = 0; kcs < DD / BK; kcs++) {
#pragma unroll
        for (int i = 0; i < 4; i++) {
            const int q   = tid + i * 256;
            const int row = q >> 3;
            const int cq  = q & 7;
            {
                const float4 v = px[i];
                const __half2 p0 = __floats2half2_rn(v.x, v.y);
                const __half2 p1 = __floats2half2_rn(v.z, v.w);
                *(uint2*)&Xs[row * RS + cq * 4] =
                    make_uint2(*(const uint32_t*)&p0, *(const uint32_t*)&p1);
            }
            {
                const float4 v = pw[i];
                const __half2 p0 = __floats2half2_rn(v.x, v.y);
                const __half2 p1 = __floats2half2_rn(v.z, v.w);
                *(uint2*)&Ws[row * RS + cq * 4] =
                    make_uint2(*(const uint32_t*)&p0, *(const uint32_t*)&p1);
            }
        }
        __syncthreads();

        if (kcs + 1 < DD / BK) {
            const int kc = (kcs + 1) * BK;
#pragma unroll
            for (int i = 0; i < 4; i++) {
                const int q   = tid + i * 256;
                const int row = q >> 3;
                const int cq  = q & 7;
                px[i] = *(const float4*)(X + (size_t)(m0 + row) * DD + kc + cq * 4);
                pw[i] = *(const float4*)(W + (size_t)row * DD + kc + cq * 4);
            }
        }

#pragma unroll
        for (int s = 0; s < BK / 16; s++) {
            const uint32_t koff = (kh + s * 16) * 2;

            uint32_t a[2][4];
#pragma unroll
            for (int am = 0; am < 2; am++) {
                const uint32_t ro = (uint32_t)(wm * 32 + am * 16 + l16) * (RS * 2) + koff;
                LDSM4(a[am][0], a[am][1], a[am][2], a[am][3], xs_b + ro);
            }
            uint32_t bb[4][4];
#pragma unroll
            for (int p = 0; p < 4; p++) {
                const uint32_t ro = (uint32_t)(wn * 64 + p * 16 + l16) * (RS * 2) + koff;
                LDSM4(bb[p][0], bb[p][1], bb[p][2], bb[p][3], ws_b + ro);
            }

#pragma unroll
            for (int p = 0; p < 4; p++)
#pragma unroll
                for (int e = 0; e < 2; e++) {
                    const int an = 2 * p + e;
#pragma unroll
                    for (int am = 0; am < 2; am++)
                        mma_f16(c[am][an], a[am][0], a[am][1], a[am][2], a[am][3],
                                bb[p][e], bb[p][2 + e]);
                }
        }
        __syncthreads();
    }

#pragma unroll
    for (int am = 0; am < 2; am++) {
        const int row = m0 + wm * 32 + am * 16 + gr;
#pragma unroll
        for (int an = 0; an < 8; an++) {
            const int col = wn * 64 + an * 8 + 2 * gc;
            *(__half2*)(H + (size_t)row * DD + col) =
                __floats2half2_rn(c[am][an][0], c[am][an][1]);
            *(__half2*)(H + (size_t)(row + 8) * DD + col) =
                __floats2half2_rn(c[am][an][2], c[am][an][3]);
        }
    }
}

// ---------------- kernel 2: gather, 2 points/warp (R11 form) --------------
__global__ void __launch_bounds__(256) gather_kernel(const __half* __restrict__ H,
                                                     const float* __restrict__ xyz,
                                                     const int* __restrict__ knn,
                                                     const float* __restrict__ coor,
                                                     const float* __restrict__ scale,
                                                     float* __restrict__ agg) {
    __shared__ float sh_s[16][132];
    __shared__ float sh_q[16][132];

    const int tid   = threadIdx.x;
    const int wloc  = tid >> 5;
    const int lane  = tid & 31;
    const int half  = lane >> 4;
    const int l16   = lane & 15;
    const int point = blockIdx.x * 16 + wloc * 2 + half;

    const int b = point >> 13;
    const int base = b << 13;

    const int g0 = 2 * l16, g1 = 2 * l16 + 1;
    const float wx0 = coor[3 * g0 + 0], wy0 = coor[3 * g0 + 1], wz0 = coor[3 * g0 + 2];
    const float wx1 = coor[3 * g1 + 0], wy1 = coor[3 * g1 + 1], wz1 = coor[3 * g1 + 2];
    const float sv0 = scale[g0], sv1 = scale[g1];
    const float ws0 = sv0 * sv0, ws1 = sv1 * sv1;

    const float* cptr = xyz + (size_t)point * 3;
    const float cx = cptr[0], cy = cptr[1], cz = cptr[2];

    const int nb = knn[(size_t)point * KK + l16];
    const float* nxp = xyz + (size_t)(base + nb) * 3;
    const float rxl = nxp[0] - cx;
    const float ryl = nxp[1] - cy;
    const float rzl = nxp[2] - cz;
    const float r2l = fmaf(rxl, rxl, fmaf(ryl, ryl, rzl * rzl));

    const float NEG = -3.402823466e38f;
    float acc[8] = {NEG, NEG, NEG, NEG, NEG, NEG, NEG, NEG};

    const __half* hbase = H + (size_t)base * DD + l16 * 8;

#pragma unroll
    for (int k = 0; k < KK; k++) {
        const int   idx = __shfl_sync(0xffffffffu, nb,  k, 16);
        const float rx  = __shfl_sync(0xffffffffu, rxl, k, 16);
        const float ry  = __shfl_sync(0xffffffffu, ryl, k, 16);
        const float rz  = __shfl_sync(0xffffffffu, rzl, k, 16);
        const float r2  = __shfl_sync(0xffffffffu, r2l, k, 16);
        const float e0  = fmaf(rx, wx0, fmaf(ry, wy0, fmaf(rz, wz0, r2 * ws0)));
        const float e1  = fmaf(rx, wx1, fmaf(ry, wy1, fmaf(rz, wz1, r2 * ws1)));

        const uint4 hv = *(const uint4*)(hbase + (size_t)idx * DD);
        const float2 f0 = __half22float2(*(const __half2*)&hv.x);
        const float2 f1 = __half22float2(*(const __half2*)&hv.y);
        const float2 f2 = __half22float2(*(const __half2*)&hv.z);
        const float2 f3 = __half22float2(*(const __half2*)&hv.w);
        acc[0] = fmaxf(acc[0], f0.x + e0);
        acc[1] = fmaxf(acc[1], f0.y + e0);
        acc[2] = fmaxf(acc[2], f1.x + e0);
        acc[3] = fmaxf(acc[3], f1.y + e0);
        acc[4] = fmaxf(acc[4], f2.x + e1);
        acc[5] = fmaxf(acc[5], f2.y + e1);
        acc[6] = fmaxf(acc[6], f3.x + e1);
        acc[7] = fmaxf(acc[7], f3.y + e1);
    }

    float* aout = agg + (size_t)point * DD + l16 * 8;
    *(float4*)(aout)     = make_float4(acc[0], acc[1], acc[2], acc[3]);
    *(float4*)(aout + 4) = make_float4(acc[4], acc[5], acc[6], acc[7]);

    const int prow = wloc * 2 + half;
    const int cb = l16 * 8;
#pragma unroll
    for (int i = 0; i < 8; i++) {
        sh_s[prow][cb + i] = acc[i];
        sh_q[prow][cb + i] = acc[i] * acc[i];
    }
    __syncthreads();

    if (tid < 128) {
        const int ch = tid;
        float s = 0.f;
#pragma unroll
        for (int p = 0; p < 16; p++) s += sh_s[p][ch];
        g_psum[blockIdx.x][ch] = s;
    } else {
        const int ch = tid - 128;
        float q = 0.f;
#pragma unroll
        for (int p = 0; p < 16; p++) q += sh_q[p][ch];
        g_psum2[blockIdx.x][ch] = q;
    }
}

// ---------------- kernel 3: stats stage A + last-block finalize -----------
__global__ void __launch_bounds__(256) statsA_kernel(const float* __restrict__ bn_w,
                                                     const float* __restrict__ bn_b) {
    __shared__ float sh[256], sh2[256];
    __shared__ int isLast;
    const int c = threadIdx.x & 127;
    const int j = threadIdx.x >> 7;
    const int p0 = blockIdx.x * 64;

    float s = 0.f, q = 0.f;
#pragma unroll 8
    for (int i = 0; i < 32; i++) {
        const int p = p0 + j + 2 * i;
        s += g_psum[p][c];
        q += g_psum2[p][c];
    }
    sh[threadIdx.x]  = s;
    sh2[threadIdx.x] = q;
    __syncthreads();
    if (j == 0) {
        g_mid [blockIdx.x][c] = sh[c]  + sh[c + 128];
        g_mid2[blockIdx.x][c] = sh2[c] + sh2[c + 128];
    }

    __threadfence();
    if (threadIdx.x == 0)
        isLast = (atomicAdd(&g_ctr, 1) == NMID - 1);
    __syncthreads();

    if (isLast) {
        float ts = 0.f, tq = 0.f;
#pragma unroll
        for (int i = 0; i < 16; i++) {
            const int p = j + 2 * i;
            ts += __ldcg(&g_mid[p][c]);
            tq += __ldcg(&g_mid2[p][c]);
        }
        sh[threadIdx.x]  = ts;
        sh2[threadIdx.x] = tq;
        __syncthreads();
        if (j == 0) {
            const float fs = sh[c] + sh[c + 128];
            const float fq = sh2[c] + sh2[c + 128];
            const float inv_m = 1.f / (float)MM;
            const float mean = fs * inv_m;
            const float var  = fmaf(-mean, mean, fq * inv_m);
            const float a = bn_w[c] * rsqrtf(var + BN_EPS);
            g_scale[c] = a;
            g_shift[c] = fmaf(-mean, a, bn_b[c]);
        }
        if (threadIdx.x == 0) g_ctr = 0;   // reset for next graph replay
    }
}

// ---------------- kernel 4: in-place normalize (R6 form) ------------------
#define NORMG 1024
__global__ void __launch_bounds__(256) norm_kernel(float* __restrict__ out) {
    const int t0 = blockIdx.x * blockDim.x + threadIdx.x;
    const int c0 = (t0 & 31) * 4;
    const float s0 = g_scale[c0 + 0], s1 = g_scale[c0 + 1];
    const float s2 = g_scale[c0 + 2], s3 = g_scale[c0 + 3];
    const float b0 = g_shift[c0 + 0], b1 = g_shift[c0 + 1];
    const float b2 = g_shift[c0 + 2], b3 = g_shift[c0 + 3];

    const int total  = MM * (DD / 4);
    const int stride = NORMG * 256;   // multiple of 32

    for (int t = t0; t < total; t += stride) {
        float4 v = __ldcs((const float4*)out + t);
        v.x = fmaf(v.x, s0, b0);
        v.y = fmaf(v.y, s1, b1);
        v.z = fmaf(v.z, s2, b2);
        v.w = fmaf(v.w, s3, b3);
        __stcs((float4*)out + t, v);
    }
}

// ---------------- launch ---------------------------------------------------
extern "C" void kernel_launch(void* const* d_in, const int* in_sizes, int n_in,
                              void* d_out, int out_size) {
    const float* x      = (const float*)d_in[0];
    const float* xyz    = (const float*)d_in[1];
    const int*   knn    = (const int*)  d_in[2];
    const float* proj_w = (const float*)d_in[3];
    const float* coor   = (const float*)d_in[4];
    const float* scale  = (const float*)d_in[5];
    const float* bn_w   = (const float*)d_in[6];
    const float* bn_b   = (const float*)d_in[7];
    float* out = (float*)d_out;

    __half* h;
    cudaGetSymbolAddress((void**)&h, g_h);

    gemm_kernel<<<MM / 128, 256>>>(x, proj_w, h);
    gather_kernel<<<MM / 16, 256>>>(h, xyz, knn, coor, scale, out);
    statsA_kernel<<<NMID, 256>>>(bn_w, bn_b);
    norm_kernel<<<NORMG, 256>>>(out);
}

// round 16
// speedup vs baseline: 1.0425x; 1.0425x over previous
#include <cuda_runtime.h>
#include <cuda_fp16.h>
#include <cstdint>

#define BB 4
#define NN 8192
#define KK 16
#define DD 128
#define GG 32
#define MM (BB*NN)          // 32768 rows
#define BN_EPS 1e-5f

#define NPART 2048          // gather blocks (16 points each) = stats partials
#define NMID 32             // stats stage-A output rows

// ---------------- scratch (device globals; no allocation) ----------------
__device__ __half g_h[(size_t)MM * DD];       // projected features, fp16, 8 MB
__device__ float g_psum [NPART][DD];
__device__ float g_psum2[NPART][DD];
__device__ float g_mid  [NMID][DD];
__device__ float g_mid2 [NMID][DD];

// ---------------- mma / ldmatrix helpers ----------------------------------
#define LDSM4(r0, r1, r2, r3, addr)                                            \
    asm volatile("ldmatrix.sync.aligned.m8n8.x4.shared.b16 {%0,%1,%2,%3}, [%4];" \
                 : "=r"(r0), "=r"(r1), "=r"(r2), "=r"(r3) : "r"(addr))

__device__ __forceinline__ void mma_f16(float c[4],
                                        uint32_t a0, uint32_t a1, uint32_t a2, uint32_t a3,
                                        uint32_t b0, uint32_t b1) {
    asm volatile(
        "mma.sync.aligned.m16n8k16.row.col.f32.f16.f16.f32 "
        "{%0,%1,%2,%3}, {%4,%5,%6,%7}, {%8,%9}, {%0,%1,%2,%3};"
        : "+f"(c[0]), "+f"(c[1]), "+f"(c[2]), "+f"(c[3])
        : "r"(a0), "r"(a1), "r"(a2), "r"(a3), "r"(b0), "r"(b1));
}

// ---------------- kernel 1: H = X * W^T, single-term fp16 HMMA ------------
#define BK 32
#define RS 40   // smem row stride in fp16 elems (80 B -> LDSM conflict-free)
__global__ void __launch_bounds__(256) gemm_kernel(const float* __restrict__ X,
                                                   const float* __restrict__ W,
                                                   __half* __restrict__ H) {
    __shared__ __half Xs[128 * RS];
    __shared__ __half Ws[128 * RS];

    const int tid  = threadIdx.x;
    const int warp = tid >> 5;
    const int lane = tid & 31;
    const int wm   = warp >> 1;
    const int wn   = warp & 1;
    const int m0   = blockIdx.x * 128;
    const int gr   = lane >> 2;
    const int gc   = lane & 3;
    const int l16  = lane & 15;
    const int kh   = (lane >> 4) << 3;

    float c[2][8][4];
#pragma unroll
    for (int i = 0; i < 2; i++)
#pragma unroll
        for (int j = 0; j < 8; j++)
#pragma unroll
            for (int t = 0; t < 4; t++) c[i][j][t] = 0.f;

    const uint32_t xs_b = (uint32_t)__cvta_generic_to_shared(Xs);
    const uint32_t ws_b = (uint32_t)__cvta_generic_to_shared(Ws);

    float4 px[4], pw[4];
#pragma unroll
    for (int i = 0; i < 4; i++) {
        const int q   = tid + i * 256;
        const int row = q >> 3;
        const int cq  = q & 7;
        px[i] = *(const float4*)(X + (size_t)(m0 + row) * DD + cq * 4);
        pw[i] = *(const float4*)(W + (size_t)row * DD + cq * 4);
    }

    for (int kcs = 0; kcs < DD / BK; kcs++) {
#pragma unroll
        for (int i = 0; i < 4; i++) {
            const int q   = tid + i * 256;
            const int row = q >> 3;
            const int cq  = q & 7;
            {
                const float4 v = px[i];
                const __half2 p0 = __floats2half2_rn(v.x, v.y);
                const __half2 p1 = __floats2half2_rn(v.z, v.w);
                *(uint2*)&Xs[row * RS + cq * 4] =
                    make_uint2(*(const uint32_t*)&p0, *(const uint32_t*)&p1);
            }
            {
                const float4 v = pw[i];
                const __half2 p0 = __floats2half2_rn(v.x, v.y);
                const __half2 p1 = __floats2half2_rn(v.z, v.w);
                *(uint2*)&Ws[row * RS + cq * 4] =
                    make_uint2(*(const uint32_t*)&p0, *(const uint32_t*)&p1);
            }
        }
        __syncthreads();

        if (kcs + 1 < DD / BK) {
            const int kc = (kcs + 1) * BK;
#pragma unroll
            for (int i = 0; i < 4; i++) {
                const int q   = tid + i * 256;
                const int row = q >> 3;
                const int cq  = q & 7;
                px[i] = *(const float4*)(X + (size_t)(m0 + row) * DD + kc + cq * 4);
                pw[i] = *(const float4*)(W + (size_t)row * DD + kc + cq * 4);
            }
        }

#pragma unroll
        for (int s = 0; s < BK / 16; s++) {
            const uint32_t koff = (kh + s * 16) * 2;

            uint32_t a[2][4];
#pragma unroll
            for (int am = 0; am < 2; am++) {
                const uint32_t ro = (uint32_t)(wm * 32 + am * 16 + l16) * (RS * 2) + koff;
                LDSM4(a[am][0], a[am][1], a[am][2], a[am][3], xs_b + ro);
            }
            uint32_t bb[4][4];
#pragma unroll
            for (int p = 0; p < 4; p++) {
                const uint32_t ro = (uint32_t)(wn * 64 + p * 16 + l16) * (RS * 2) + koff;
                LDSM4(bb[p][0], bb[p][1], bb[p][2], bb[p][3], ws_b + ro);
            }

#pragma unroll
            for (int p = 0; p < 4; p++)
#pragma unroll
                for (int e = 0; e < 2; e++) {
                    const int an = 2 * p + e;
#pragma unroll
                    for (int am = 0; am < 2; am++)
                        mma_f16(c[am][an], a[am][0], a[am][1], a[am][2], a[am][3],
                                bb[p][e], bb[p][2 + e]);
                }
        }
        __syncthreads();
    }

#pragma unroll
    for (int am = 0; am < 2; am++) {
        const int row = m0 + wm * 32 + am * 16 + gr;
#pragma unroll
        for (int an = 0; an < 8; an++) {
            const int col = wn * 64 + an * 8 + 2 * gc;
            *(__half2*)(H + (size_t)row * DD + col) =
                __floats2half2_rn(c[am][an][0], c[am][an][1]);
            *(__half2*)(H + (size_t)(row + 8) * DD + col) =
                __floats2half2_rn(c[am][an][2], c[am][an][3]);
        }
    }
}

// ---------------- kernel 2: gather, 2 points/warp (R11 form) --------------
__global__ void __launch_bounds__(256) gather_kernel(const __half* __restrict__ H,
                                                     const float* __restrict__ xyz,
                                                     const int* __restrict__ knn,
                                                     const float* __restrict__ coor,
                                                     const float* __restrict__ scale,
                                                     float* __restrict__ agg) {
    __shared__ float sh_s[16][132];
    __shared__ float sh_q[16][132];

    const int tid   = threadIdx.x;
    const int wloc  = tid >> 5;
    const int lane  = tid & 31;
    const int half  = lane >> 4;
    const int l16   = lane & 15;
    const int point = blockIdx.x * 16 + wloc * 2 + half;

    const int b = point >> 13;
    const int base = b << 13;

    const int g0 = 2 * l16, g1 = 2 * l16 + 1;
    const float wx0 = coor[3 * g0 + 0], wy0 = coor[3 * g0 + 1], wz0 = coor[3 * g0 + 2];
    const float wx1 = coor[3 * g1 + 0], wy1 = coor[3 * g1 + 1], wz1 = coor[3 * g1 + 2];
    const float sv0 = scale[g0], sv1 = scale[g1];
    const float ws0 = sv0 * sv0, ws1 = sv1 * sv1;

    const float* cptr = xyz + (size_t)point * 3;
    const float cx = cptr[0], cy = cptr[1], cz = cptr[2];

    const int nb = knn[(size_t)point * KK + l16];
    const float* nxp = xyz + (size_t)(base + nb) * 3;
    const float rxl = nxp[0] - cx;
    const float ryl = nxp[1] - cy;
    const float rzl = nxp[2] - cz;
    const float r2l = fmaf(rxl, rxl, fmaf(ryl, ryl, rzl * rzl));

    const float NEG = -3.402823466e38f;
    float acc[8] = {NEG, NEG, NEG, NEG, NEG, NEG, NEG, NEG};

    const __half* hbase = H + (size_t)base * DD + l16 * 8;

#pragma unroll
    for (int k = 0; k < KK; k++) {
        const int   idx = __shfl_sync(0xffffffffu, nb,  k, 16);
        const float rx  = __shfl_sync(0xffffffffu, rxl, k, 16);
        const float ry  = __shfl_sync(0xffffffffu, ryl, k, 16);
        const float rz  = __shfl_sync(0xffffffffu, rzl, k, 16);
        const float r2  = __shfl_sync(0xffffffffu, r2l, k, 16);
        const float e0  = fmaf(rx, wx0, fmaf(ry, wy0, fmaf(rz, wz0, r2 * ws0)));
        const float e1  = fmaf(rx, wx1, fmaf(ry, wy1, fmaf(rz, wz1, r2 * ws1)));

        const uint4 hv = *(const uint4*)(hbase + (size_t)idx * DD);
        const float2 f0 = __half22float2(*(const __half2*)&hv.x);
        const float2 f1 = __half22float2(*(const __half2*)&hv.y);
        const float2 f2 = __half22float2(*(const __half2*)&hv.z);
        const float2 f3 = __half22float2(*(const __half2*)&hv.w);
        acc[0] = fmaxf(acc[0], f0.x + e0);
        acc[1] = fmaxf(acc[1], f0.y + e0);
        acc[2] = fmaxf(acc[2], f1.x + e0);
        acc[3] = fmaxf(acc[3], f1.y + e0);
        acc[4] = fmaxf(acc[4], f2.x + e1);
        acc[5] = fmaxf(acc[5], f2.y + e1);
        acc[6] = fmaxf(acc[6], f3.x + e1);
        acc[7] = fmaxf(acc[7], f3.y + e1);
    }

    float* aout = agg + (size_t)point * DD + l16 * 8;
    *(float4*)(aout)     = make_float4(acc[0], acc[1], acc[2], acc[3]);
    *(float4*)(aout + 4) = make_float4(acc[4], acc[5], acc[6], acc[7]);

    const int prow = wloc * 2 + half;
    const int cb = l16 * 8;
#pragma unroll
    for (int i = 0; i < 8; i++) {
        sh_s[prow][cb + i] = acc[i];
        sh_q[prow][cb + i] = acc[i] * acc[i];
    }
    __syncthreads();

    if (tid < 128) {
        const int ch = tid;
        float s = 0.f;
#pragma unroll
        for (int p = 0; p < 16; p++) s += sh_s[p][ch];
        g_psum[blockIdx.x][ch] = s;
    } else {
        const int ch = tid - 128;
        float q = 0.f;
#pragma unroll
        for (int p = 0; p < 16; p++) q += sh_q[p][ch];
        g_psum2[blockIdx.x][ch] = q;
    }
}

// ---------------- kernel 3: stats stage A (coalesced, 2048 -> 32 rows) ----
__global__ void __launch_bounds__(256) statsA_kernel() {
    __shared__ float sh[256], sh2[256];
    const int c = threadIdx.x & 127;
    const int j = threadIdx.x >> 7;
    const int p0 = blockIdx.x * 64;

    float s = 0.f, q = 0.f;
#pragma unroll 8
    for (int i = 0; i < 32; i++) {
        const int p = p0 + j + 2 * i;
        s += g_psum[p][c];
        q += g_psum2[p][c];
    }
    sh[threadIdx.x]  = s;
    sh2[threadIdx.x] = q;
    __syncthreads();
    if (j == 0) {
        g_mid [blockIdx.x][c] = sh[c]  + sh[c + 128];
        g_mid2[blockIdx.x][c] = sh2[c] + sh2[c + 128];
    }
}

// ---------------- kernel 4: finalize stats (per-block) + normalize --------
#define NORMG 256
__global__ void __launch_bounds__(256) norm_kernel(float* __restrict__ out,
                                                   const float* __restrict__ bn_w,
                                                   const float* __restrict__ bn_b) {
    __shared__ float sh[2][DD], sh2[2][DD], sa[DD], sb[DD];
    const int c = threadIdx.x & 127;
    const int j = threadIdx.x >> 7;

    float s = 0.f, q = 0.f;
#pragma unroll
    for (int i = 0; i < 16; i++) {
        const int p = j + 2 * i;
        s += g_mid[p][c];
        q += g_mid2[p][c];
    }
    sh[j][c]  = s;
    sh2[j][c] = q;
    __syncthreads();
    if (j == 0) {
        const float ts = sh[0][c] + sh[1][c];
        const float tq = sh2[0][c] + sh2[1][c];
        const float inv_m = 1.f / (float)MM;
        const float mean = ts * inv_m;
        const float var  = fmaf(-mean, mean, tq * inv_m);
        const float a = bn_w[c] * rsqrtf(var + BN_EPS);
        sa[c] = a;
        sb[c] = fmaf(-mean, a, bn_b[c]);
    }
    __syncthreads();

    const int t0 = blockIdx.x * blockDim.x + threadIdx.x;
    const int c0 = (t0 & 31) * 4;
    const float s0 = sa[c0 + 0], s1 = sa[c0 + 1], s2 = sa[c0 + 2], s3 = sa[c0 + 3];
    const float b0 = sb[c0 + 0], b1 = sb[c0 + 1], b2 = sb[c0 + 2], b3 = sb[c0 + 3];

    const int total  = MM * (DD / 4);
    const int stride = NORMG * 256;   // multiple of 32

    for (int t = t0; t < total; t += stride) {
        float4 v = __ldcs((const float4*)out + t);
        v.x = fmaf(v.x, s0, b0);
        v.y = fmaf(v.y, s1, b1);
        v.z = fmaf(v.z, s2, b2);
        v.w = fmaf(v.w, s3, b3);
        __stcs((float4*)out + t, v);
    }
}

// ---------------- launch ---------------------------------------------------
extern "C" void kernel_launch(void* const* d_in, const int* in_sizes, int n_in,
                              void* d_out, int out_size) {
    const float* x      = (const float*)d_in[0];
    const float* xyz    = (const float*)d_in[1];
    const int*   knn    = (const int*)  d_in[2];
    const float* proj_w = (const float*)d_in[3];
    const float* coor   = (const float*)d_in[4];
    const float* scale  = (const float*)d_in[5];
    const float* bn_w   = (const float*)d_in[6];
    const float* bn_b   = (const float*)d_in[7];
    float* out = (float*)d_out;

    __half* h;
    cudaGetSymbolAddress((void**)&h, g_h);

    gemm_kernel<<<MM / 128, 256>>>(x, proj_w, h);
    gather_kernel<<<MM / 16, 256>>>(h, xyz, knn, coor, scale, out);
    statsA_kernel<<<32, 256>>>();
    norm_kernel<<<NORMG, 256>>>(out, bn_w, bn_b);
}

// round 17
// speedup vs baseline: 1.0674x; 1.0239x over previous
#include <cuda_runtime.h>
#include <cuda_fp16.h>
#include <cstdint>

#define BB 4
#define NN 8192
#define KK 16
#define DD 128
#define GG 32
#define MM (BB*NN)          // 32768 rows
#define BN_EPS 1e-5f

#define NPART 2048          // gather blocks (16 points each) = stats partials
#define NMID 32             // stats stage-A output rows

// ---------------- scratch (device globals; no allocation) ----------------
__device__ __half g_h[(size_t)MM * DD];       // projected features, fp16, 8 MB
__device__ float g_psum [NPART][DD];
__device__ float g_psum2[NPART][DD];
__device__ float g_mid  [NMID][DD];
__device__ float g_mid2 [NMID][DD];

// ---------------- mma / ldmatrix helpers ----------------------------------
#define LDSM4(r0, r1, r2, r3, addr)                                            \
    asm volatile("ldmatrix.sync.aligned.m8n8.x4.shared.b16 {%0,%1,%2,%3}, [%4];" \
                 : "=r"(r0), "=r"(r1), "=r"(r2), "=r"(r3) : "r"(addr))

__device__ __forceinline__ void mma_f16(float c[4],
                                        uint32_t a0, uint32_t a1, uint32_t a2, uint32_t a3,
                                        uint32_t b0, uint32_t b1) {
    asm volatile(
        "mma.sync.aligned.m16n8k16.row.col.f32.f16.f16.f32 "
        "{%0,%1,%2,%3}, {%4,%5,%6,%7}, {%8,%9}, {%0,%1,%2,%3};"
        : "+f"(c[0]), "+f"(c[1]), "+f"(c[2]), "+f"(c[3])
        : "r"(a0), "r"(a1), "r"(a2), "r"(a3), "r"(b0), "r"(b1));
}

// ---------------- kernel 1: H = X * W^T, single-term fp16 HMMA ------------
#define BK 32
#define RS 40   // smem row stride in fp16 elems (80 B -> LDSM conflict-free)
__global__ void __launch_bounds__(256) gemm_kernel(const float* __restrict__ X,
                                                   const float* __restrict__ W,
                                                   __half* __restrict__ H) {
    __shared__ __half Xs[128 * RS];
    __shared__ __half Ws[128 * RS];

    const int tid  = threadIdx.x;
    const int warp = tid >> 5;
    const int lane = tid & 31;
    const int wm   = warp >> 1;
    const int wn   = warp & 1;
    const int m0   = blockIdx.x * 128;
    const int gr   = lane >> 2;
    const int gc   = lane & 3;
    const int l16  = lane & 15;
    const int kh   = (lane >> 4) << 3;

    float c[2][8][4];
#pragma unroll
    for (int i = 0; i < 2; i++)
#pragma unroll
        for (int j = 0; j < 8; j++)
#pragma unroll
            for (int t = 0; t < 4; t++) c[i][j][t] = 0.f;

    const uint32_t xs_b = (uint32_t)__cvta_generic_to_shared(Xs);
    const uint32_t ws_b = (uint32_t)__cvta_generic_to_shared(Ws);

    float4 px[4], pw[4];
#pragma unroll
    for (int i = 0; i < 4; i++) {
        const int q   = tid + i * 256;
        const int row = q >> 3;
        const int cq  = q & 7;
        px[i] = *(const float4*)(X + (size_t)(m0 + row) * DD + cq * 4);
        pw[i] = *(const float4*)(W + (size_t)row * DD + cq * 4);
    }

    for (int kcs = 0; kcs < DD / BK; kcs++) {
#pragma unroll
        for (int i = 0; i < 4; i++) {
            const int q   = tid + i * 256;
            const int row = q >> 3;
            const int cq  = q & 7;
            {
                const float4 v = px[i];
                const __half2 p0 = __floats2half2_rn(v.x, v.y);
                const __half2 p1 = __floats2half2_rn(v.z, v.w);
                *(uint2*)&Xs[row * RS + cq * 4] =
                    make_uint2(*(const uint32_t*)&p0, *(const uint32_t*)&p1);
            }
            {
                const float4 v = pw[i];
                const __half2 p0 = __floats2half2_rn(v.x, v.y);
                const __half2 p1 = __floats2half2_rn(v.z, v.w);
                *(uint2*)&Ws[row * RS + cq * 4] =
                    make_uint2(*(const uint32_t*)&p0, *(const uint32_t*)&p1);
            }
        }
        __syncthreads();

        if (kcs + 1 < DD / BK) {
            const int kc = (kcs + 1) * BK;
#pragma unroll
            for (int i = 0; i < 4; i++) {
                const int q   = tid + i * 256;
                const int row = q >> 3;
                const int cq  = q & 7;
                px[i] = *(const float4*)(X + (size_t)(m0 + row) * DD + kc + cq * 4);
                pw[i] = *(const float4*)(W + (size_t)row * DD + kc + cq * 4);
            }
        }

#pragma unroll
        for (int s = 0; s < BK / 16; s++) {
            const uint32_t koff = (kh + s * 16) * 2;

            uint32_t a[2][4];
#pragma unroll
            for (int am = 0; am < 2; am++) {
                const uint32_t ro = (uint32_t)(wm * 32 + am * 16 + l16) * (RS * 2) + koff;
                LDSM4(a[am][0], a[am][1], a[am][2], a[am][3], xs_b + ro);
            }
            uint32_t bb[4][4];
#pragma unroll
            for (int p = 0; p < 4; p++) {
                const uint32_t ro = (uint32_t)(wn * 64 + p * 16 + l16) * (RS * 2) + koff;
                LDSM4(bb[p][0], bb[p][1], bb[p][2], bb[p][3], ws_b + ro);
            }

#pragma unroll
            for (int p = 0; p < 4; p++)
#pragma unroll
                for (int e = 0; e < 2; e++) {
                    const int an = 2 * p + e;
#pragma unroll
                    for (int am = 0; am < 2; am++)
                        mma_f16(c[am][an], a[am][0], a[am][1], a[am][2], a[am][3],
                                bb[p][e], bb[p][2 + e]);
                }
        }
        __syncthreads();
    }

#pragma unroll
    for (int am = 0; am < 2; am++) {
        const int row = m0 + wm * 32 + am * 16 + gr;
#pragma unroll
        for (int an = 0; an < 8; an++) {
            const int col = wn * 64 + an * 8 + 2 * gc;
            *(__half2*)(H + (size_t)row * DD + col) =
                __floats2half2_rn(c[am][an][0], c[am][an][1]);
            *(__half2*)(H + (size_t)(row + 8) * DD + col) =
                __floats2half2_rn(c[am][an][2], c[am][an][3]);
        }
    }
}

// ---------------- kernel 2: gather, 2 points/warp, half2 max path ---------
__global__ void __launch_bounds__(256) gather_kernel(const __half* __restrict__ H,
                                                     const float* __restrict__ xyz,
                                                     const int* __restrict__ knn,
                                                     const float* __restrict__ coor,
                                                     const float* __restrict__ scale,
                                                     float* __restrict__ agg) {
    __shared__ float sh_s[16][132];
    __shared__ float sh_q[16][132];

    const int tid   = threadIdx.x;
    const int wloc  = tid >> 5;
    const int lane  = tid & 31;
    const int half  = lane >> 4;
    const int l16   = lane & 15;
    const int point = blockIdx.x * 16 + wloc * 2 + half;

    const int b = point >> 13;
    const int base = b << 13;

    const int g0 = 2 * l16, g1 = 2 * l16 + 1;
    const float wx0 = coor[3 * g0 + 0], wy0 = coor[3 * g0 + 1], wz0 = coor[3 * g0 + 2];
    const float wx1 = coor[3 * g1 + 0], wy1 = coor[3 * g1 + 1], wz1 = coor[3 * g1 + 2];
    const float sv0 = scale[g0], sv1 = scale[g1];
    const float ws0 = sv0 * sv0, ws1 = sv1 * sv1;

    const float* cptr = xyz + (size_t)point * 3;
    const float cx = cptr[0], cy = cptr[1], cz = cptr[2];

    const int nb = knn[(size_t)point * KK + l16];
    const float* nxp = xyz + (size_t)(base + nb) * 3;
    const float rxl = nxp[0] - cx;
    const float ryl = nxp[1] - cy;
    const float rzl = nxp[2] - cz;
    const float r2l = fmaf(rxl, rxl, fmaf(ryl, ryl, rzl * rzl));

    // fp16 max accumulators (4 half2 = 8 channels), init -inf
    const __half2 NEG2 = __halves2half2(__ushort_as_half(0xFC00),
                                        __ushort_as_half(0xFC00));
    __half2 acc2[4] = {NEG2, NEG2, NEG2, NEG2};

    const __half* hbase = H + (size_t)base * DD + l16 * 8;

#pragma unroll
    for (int k = 0; k < KK; k++) {
        const int   idx = __shfl_sync(0xffffffffu, nb,  k, 16);
        const float rx  = __shfl_sync(0xffffffffu, rxl, k, 16);
        const float ry  = __shfl_sync(0xffffffffu, ryl, k, 16);
        const float rz  = __shfl_sync(0xffffffffu, rzl, k, 16);
        const float r2  = __shfl_sync(0xffffffffu, r2l, k, 16);
        const float e0  = fmaf(rx, wx0, fmaf(ry, wy0, fmaf(rz, wz0, r2 * ws0)));
        const float e1  = fmaf(rx, wx1, fmaf(ry, wy1, fmaf(rz, wz1, r2 * ws1)));
        const __half2 e0h = __float2half2_rn(e0);
        const __half2 e1h = __float2half2_rn(e1);

        const uint4 hv = *(const uint4*)(hbase + (size_t)idx * DD);
        acc2[0] = __hmax2(acc2[0], __hadd2(*(const __half2*)&hv.x, e0h));
        acc2[1] = __hmax2(acc2[1], __hadd2(*(const __half2*)&hv.y, e0h));
        acc2[2] = __hmax2(acc2[2], __hadd2(*(const __half2*)&hv.z, e1h));
        acc2[3] = __hmax2(acc2[3], __hadd2(*(const __half2*)&hv.w, e1h));
    }

    // unpack to fp32 for agg store + stats
    const float2 a0 = __half22float2(acc2[0]);
    const float2 a1 = __half22float2(acc2[1]);
    const float2 a2 = __half22float2(acc2[2]);
    const float2 a3 = __half22float2(acc2[3]);
    float acc[8] = {a0.x, a0.y, a1.x, a1.y, a2.x, a2.y, a3.x, a3.y};

    float* aout = agg + (size_t)point * DD + l16 * 8;
    *(float4*)(aout)     = make_float4(acc[0], acc[1], acc[2], acc[3]);
    *(float4*)(aout + 4) = make_float4(acc[4], acc[5], acc[6], acc[7]);

    const int prow = wloc * 2 + half;
    const int cb = l16 * 8;
#pragma unroll
    for (int i = 0; i < 8; i++) {
        sh_s[prow][cb + i] = acc[i];
        sh_q[prow][cb + i] = acc[i] * acc[i];
    }
    __syncthreads();

    if (tid < 128) {
        const int ch = tid;
        float s = 0.f;
#pragma unroll
        for (int p = 0; p < 16; p++) s += sh_s[p][ch];
        g_psum[blockIdx.x][ch] = s;
    } else {
        const int ch = tid - 128;
        float q = 0.f;
#pragma unroll
        for (int p = 0; p < 16; p++) q += sh_q[p][ch];
        g_psum2[blockIdx.x][ch] = q;
    }
}

// ---------------- kernel 3: stats stage A (coalesced, 2048 -> 32 rows) ----
__global__ void __launch_bounds__(256) statsA_kernel() {
    __shared__ float sh[256], sh2[256];
    const int c = threadIdx.x & 127;
    const int j = threadIdx.x >> 7;
    const int p0 = blockIdx.x * 64;

    float s = 0.f, q = 0.f;
#pragma unroll 8
    for (int i = 0; i < 32; i++) {
        const int p = p0 + j + 2 * i;
        s += g_psum[p][c];
        q += g_psum2[p][c];
    }
    sh[threadIdx.x]  = s;
    sh2[threadIdx.x] = q;
    __syncthreads();
    if (j == 0) {
        g_mid [blockIdx.x][c] = sh[c]  + sh[c + 128];
        g_mid2[blockIdx.x][c] = sh2[c] + sh2[c + 128];
    }
}

// ---------------- kernel 4: finalize stats (per-block) + normalize --------
#define NORMG 256
__global__ void __launch_bounds__(256) norm_kernel(float* __restrict__ out,
                                                   const float* __restrict__ bn_w,
                                                   const float* __restrict__ bn_b) {
    __shared__ float sh[2][DD], sh2[2][DD], sa[DD], sb[DD];
    const int c = threadIdx.x & 127;
    const int j = threadIdx.x >> 7;

    float s = 0.f, q = 0.f;
#pragma unroll
    for (int i = 0; i < 16; i++) {
        const int p = j + 2 * i;
        s += g_mid[p][c];
        q += g_mid2[p][c];
    }
    sh[j][c]  = s;
    sh2[j][c] = q;
    __syncthreads();
    if (j == 0) {
        const float ts = sh[0][c] + sh[1][c];
        const float tq = sh2[0][c] + sh2[1][c];
        const float inv_m = 1.f / (float)MM;
        const float mean = ts * inv_m;
        const float var  = fmaf(-mean, mean, tq * inv_m);
        const float a = bn_w[c] * rsqrtf(var + BN_EPS);
        sa[c] = a;
        sb[c] = fmaf(-mean, a, bn_b[c]);
    }
    __syncthreads();

    const int t0 = blockIdx.x * blockDim.x + threadIdx.x;
    const int c0 = (t0 & 31) * 4;
    const float s0 = sa[c0 + 0], s1 = sa[c0 + 1], s2 = sa[c0 + 2], s3 = sa[c0 + 3];
    const float b0 = sb[c0 + 0], b1 = sb[c0 + 1], b2 = sb[c0 + 2], b3 = sb[c0 + 3];

    const int total  = MM * (DD / 4);
    const int stride = NORMG * 256;   // multiple of 32

    for (int t = t0; t < total; t += stride) {
        float4 v = __ldcs((const float4*)out + t);
        v.x = fmaf(v.x, s0, b0);
        v.y = fmaf(v.y, s1, b1);
        v.z = fmaf(v.z, s2, b2);
        v.w = fmaf(v.w, s3, b3);
        __stcs((float4*)out + t, v);
    }
}

// ---------------- launch ---------------------------------------------------
extern "C" void kernel_launch(void* const* d_in, const int* in_sizes, int n_in,
                              void* d_out, int out_size) {
    const float* x      = (const float*)d_in[0];
    const float* xyz    = (const float*)d_in[1];
    const int*   knn    = (const int*)  d_in[2];
    const float* proj_w = (const float*)d_in[3];
    const float* coor   = (const float*)d_in[4];
    const float* scale  = (const float*)d_in[5];
    const float* bn_w   = (const float*)d_in[6];
    const float* bn_b   = (const float*)d_in[7];
    float* out = (float*)d_out;

    __half* h;
    cudaGetSymbolAddress((void**)&h, g_h);

    gemm_kernel<<<MM / 128, 256>>>(x, proj_w, h);
    gather_kernel<<<MM / 16, 256>>>(h, xyz, knn, coor, scale, out);
    statsA_kernel<<<32, 256>>>();
    norm_kernel<<<NORMG, 256>>>(out, bn_w, bn_b);
}